// round 16
// baseline (speedup 1.0000x reference)
#include <cuda_runtime.h>
#include <cuda_fp16.h>
#include <cstddef>

#define BATCH 4096

// ---------------------------------------------------------------------------
// Scratch (static __device__; no cudaMalloc allowed)
// ---------------------------------------------------------------------------
__device__ unsigned g_h2[(size_t)BATCH * 9216];   // conv2+pool out, packed (hi|lo<<16) split-fp16
__device__ float    g_h3[(size_t)BATCH * 128];    // fc1 out
__device__ float    g_sig[10 * 10 * 10];          // Sigma_inv
__device__ float    g_det[10];                    // det_scale
__device__ unsigned g_wph[9216];                  // conv2 W (single fp16), uint4 layout [ks][ntp][lane][4]
__device__ unsigned g_f1w[4608 * 128];            // fc1 W single fp16, paired fp16x2 [k/2][n]

// ---------------------------------------------------------------------------
// helpers
// ---------------------------------------------------------------------------
__device__ __forceinline__ void split_fp16(float v, unsigned& h, unsigned& l) {
    __half hb = __float2half_rn(v);
    float hf = __half2float(hb);
    __half lb = __float2half_rn(v - hf);
    h = (unsigned)__half_as_ushort(hb);
    l = (unsigned)__half_as_ushort(lb);
}

#define MMAF16(Cr, Ar, b0, b1)                                                \
    asm volatile("mma.sync.aligned.m16n8k16.row.col.f32.f16.f16.f32 "         \
                 "{%0,%1,%2,%3}, {%4,%5,%6,%7}, {%8,%9}, {%0,%1,%2,%3};"      \
                 : "+f"(Cr[0]), "+f"(Cr[1]), "+f"(Cr[2]), "+f"(Cr[3])         \
                 : "r"(Ar[0]), "r"(Ar[1]), "r"(Ar[2]), "r"(Ar[3]),            \
                   "r"(b0), "r"(b1))

// ---------------------------------------------------------------------------
// GMM precompute (unchanged)
// ---------------------------------------------------------------------------
__global__ void k_gmm_pre(const float* __restrict__ raw) {
    int k = threadIdx.x;
    if (k >= 10) return;
    const float* R = raw + k * 100;

    float D[10];
#pragma unroll
    for (int i = 0; i < 10; i++) { float r = R[i * 10 + i]; D[i] = r * r + 1e-4f; }

    float Li[10][10];
#pragma unroll
    for (int i = 0; i < 10; i++)
#pragma unroll
        for (int j = 0; j < 10; j++) Li[i][j] = (i == j) ? 1.f : 0.f;

    for (int j = 0; j < 10; j++)
        for (int i = j + 1; i < 10; i++) {
            float s = 0.f;
            for (int m = j; m < i; m++) s = fmaf(R[i * 10 + m], Li[m][j], s);
            Li[i][j] = -s;
        }

    for (int i = 0; i < 10; i++)
        for (int j = 0; j < 10; j++) {
            int a0 = (i > j) ? i : j;
            float s = 0.f;
            for (int a = a0; a < 10; a++) s += Li[a][i] * Li[a][j] / D[a];
            g_sig[k * 100 + i * 10 + j] = s;
        }

    float p = 1.f;
#pragma unroll
    for (int a = 0; a < 10; a++) p *= D[a];
    g_det[k] = rsqrtf(p);
}

// ---------------------------------------------------------------------------
// conv2 weight prep, uint4-load layout (single fp16 per weight).
// ---------------------------------------------------------------------------
__global__ void k_wprep(const float* __restrict__ w2) {
    int t = blockIdx.x * 256 + threadIdx.x;
    if (t >= 9216) return;
    int j    = t & 3;
    int lane = (t >> 2) & 31;
    int ntp  = (t >> 7) & 3;
    int ks   = t >> 9;
    int g = lane >> 2, tg = lane & 3;
    int h = j & 1, nt = 2 * ntp + (j >> 1);

    int kp = ks * 8 + h * 4 + tg;
    int n  = nt * 8 + g;
    int w  = kp >> 4;
    int ci = (kp & 15) * 2;
    int dy = w / 3, dx = w - dy * 3;

    unsigned v0 = (unsigned)__half_as_ushort(
        __float2half_rn(w2[((n * 32 + ci) * 3 + dy) * 3 + dx]));
    unsigned v1 = (unsigned)__half_as_ushort(
        __float2half_rn(w2[((n * 32 + ci + 1) * 3 + dy) * 3 + dx]));
    g_wph[t] = v0 | (v1 << 16);
}

// ---------------------------------------------------------------------------
// fc1 weight prep: single fp16 pairs [k/2][n]
// ---------------------------------------------------------------------------
__global__ void k_f1prep(const float* __restrict__ W) {
    __shared__ unsigned sh[32][132];
    const int kp0 = blockIdx.x * 32;      // 144 blocks
    const int t = threadIdx.x;            // 256
    const int n = t >> 1, half = t & 1;

    const float* src = W + (size_t)n * 9216 + kp0 * 2 + half * 32;
#pragma unroll
    for (int j = 0; j < 16; j++) {
        unsigned h0 = (unsigned)__half_as_ushort(__float2half_rn(src[2 * j]));
        unsigned h1 = (unsigned)__half_as_ushort(__float2half_rn(src[2 * j + 1]));
        sh[half * 16 + j][n] = h0 | (h1 << 16);
    }
    __syncthreads();

    const int kpl = t >> 3, c0 = (t & 7) * 16;
    unsigned* dh = &g_f1w[(size_t)(kp0 + kpl) * 128 + c0];
#pragma unroll
    for (int j = 0; j < 4; j++)
        ((uint4*)dh)[j] = ((uint4*)&sh[kpl][c0])[j];
}

// ---------------------------------------------------------------------------
// Fused conv1 + conv2 + relu + maxpool, 2-term split-fp16 HMMA.
// One block = one image, 576 threads (18 warps), 2 m16-strips x 8 n8-tiles.
// Epilogue staged through smem (stride-148 padded, conflict-free) and
// flushed with coalesced uint4 stores; conv2 bias (64 ch!) in smem.
// ---------------------------------------------------------------------------
__global__ void __launch_bounds__(576, 1)
k_convfused(const float* __restrict__ x,
            const float* __restrict__ w1,
            const float* __restrict__ b1,
            const float* __restrict__ cb) {
    const int b   = blockIdx.x;
    const int tid = threadIdx.x;
    const int lane = tid & 31, wid = tid >> 5;
    const int g = lane >> 2, tg = lane & 3;

    extern __shared__ char smraw[];
    unsigned short* sAh = (unsigned short*)smraw;               // [676][34] u16 (fp16 hi)
    unsigned short* sAl = (unsigned short*)(smraw + 46080);     // [676][34] u16 (fp16 lo)
    unsigned* sB   = (unsigned*)(smraw + 92160);                // [9216] u32 (fp16x2 W)
    unsigned* sOut = (unsigned*)(smraw + 129024);               // [64][148] u32 staged output
    float*    sX   = (float*)(smraw + 166912);                  // [784]
    float*    sW1  = (float*)(smraw + 170048);                  // [288]
    float*    sB1  = (float*)(smraw + 171200);                  // [32]
    float*    sCB  = (float*)(smraw + 171328);                  // [64] conv2 bias (FULL 64 ch)
    const unsigned* sA32h = (const unsigned*)sAh;
    const unsigned* sA32l = (const unsigned*)sAl;

    for (int i = tid; i < 9216; i += 576) sB[i] = g_wph[i];
    for (int i = tid; i < 784; i += 576) sX[i] = x[(size_t)b * 784 + i];
    if (tid < 288) sW1[tid] = w1[tid];
    if (tid < 32) sB1[tid] = b1[tid];
    if (tid < 64) sCB[tid] = cb[tid];
    __syncthreads();

    // conv1 -> relu -> split-fp16, channel-interleaved
    for (int idx = tid; idx < 21632; idx += 576) {
        int c = idx / 676, p = idx - c * 676;
        int y = p / 26, xx = p - y * 26;
        float acc = sB1[c];
        const float* xp = sX + y * 28 + xx;
        const float* wp = sW1 + c * 9;
#pragma unroll
        for (int dy = 0; dy < 3; dy++)
#pragma unroll
            for (int dx = 0; dx < 3; dx++)
                acc = fmaf(xp[dy * 28 + dx], wp[dy * 3 + dx], acc);
        float v = fmaxf(acc, 0.f);
        unsigned h, l; split_fp16(v, h, l);
        sAh[p * 34 + c] = (unsigned short)h;
        sAl[p * 34 + c] = (unsigned short)l;
    }
    __syncthreads();

    // per-(strip,row-half) A row base * 17 (u32 stride of a 34-u16 row)
    int base17[2][2];
#pragma unroll
    for (int st = 0; st < 2; st++)
#pragma unroll
        for (int h = 0; h < 2; h++) {
            int m = (wid * 2 + st) * 16 + g + h * 8;
            int quad = m >> 2, e = m & 3;
            int py = quad / 12, px = quad - py * 12;
            base17[st][h] = ((py * 2 + (e >> 1)) * 26 + px * 2 + (e & 1)) * 17;
        }

    float C[2][8][4];
#pragma unroll
    for (int st = 0; st < 2; st++)
#pragma unroll
        for (int nt = 0; nt < 8; nt++)
#pragma unroll
            for (int q = 0; q < 4; q++) C[st][nt][q] = 0.f;

#pragma unroll 1
    for (int ks = 0; ks < 18; ks++) {
        const int w = ks >> 1;
        const int dy = w / 3;
        const int off17 = (dy * 26 + (w - dy * 3)) * 17;
        const int cA = (ks & 1) * 8 + tg;

        // ---- hoisted A fragments for both strips (16 regs: xh and xl) ----
        unsigned ah[2][4], al[2][4];
#pragma unroll
        for (int st = 0; st < 2; st++) {
            const int r0 = base17[st][0] + off17 + cA;
            const int r1 = base17[st][1] + off17 + cA;
            ah[st][0] = sA32h[r0];     al[st][0] = sA32l[r0];
            ah[st][1] = sA32h[r1];     al[st][1] = sA32l[r1];
            ah[st][2] = sA32h[r0 + 4]; al[st][2] = sA32l[r0 + 4];
            ah[st][3] = sA32h[r1 + 4]; al[st][3] = sA32l[r1 + 4];
        }

        // ---- n-tile pairs: one LDS.128 then 8 MMAs (same-C spacing 4) ----
        const uint4* bp = ((const uint4*)sB) + ks * 128 + lane;
#pragma unroll
        for (int ntp = 0; ntp < 4; ntp++) {
            const uint4 Bq = bp[ntp * 32];
            const int nt0 = 2 * ntp, nt1 = nt0 + 1;
            MMAF16(C[0][nt0], ah[0], Bq.x, Bq.y);
            MMAF16(C[1][nt0], ah[1], Bq.x, Bq.y);
            MMAF16(C[0][nt1], ah[0], Bq.z, Bq.w);
            MMAF16(C[1][nt1], ah[1], Bq.z, Bq.w);
            MMAF16(C[0][nt0], al[0], Bq.x, Bq.y);
            MMAF16(C[1][nt0], al[1], Bq.x, Bq.y);
            MMAF16(C[0][nt1], al[0], Bq.z, Bq.w);
            MMAF16(C[1][nt1], al[1], Bq.z, Bq.w);
        }
    }

    // maxpool via shfl + bias + relu + split-fp16 pack -> staged to sOut
#pragma unroll
    for (int st = 0; st < 2; st++) {
        const int s = wid * 2 + st;
#pragma unroll
        for (int nt = 0; nt < 8; nt++) {
            float v0 = C[st][nt][0], v1 = C[st][nt][1];
            float v2 = C[st][nt][2], v3 = C[st][nt][3];
            v0 = fmaxf(v0, __shfl_xor_sync(0xffffffffu, v0, 4));
            v0 = fmaxf(v0, __shfl_xor_sync(0xffffffffu, v0, 8));
            v1 = fmaxf(v1, __shfl_xor_sync(0xffffffffu, v1, 4));
            v1 = fmaxf(v1, __shfl_xor_sync(0xffffffffu, v1, 8));
            v2 = fmaxf(v2, __shfl_xor_sync(0xffffffffu, v2, 4));
            v2 = fmaxf(v2, __shfl_xor_sync(0xffffffffu, v2, 8));
            v3 = fmaxf(v3, __shfl_xor_sync(0xffffffffu, v3, 4));
            v3 = fmaxf(v3, __shfl_xor_sync(0xffffffffu, v3, 8));
            if ((lane & 12) == 0) {
                int a  = lane >> 4;
                int qA = s * 4 + a, qB = qA + 2;
                int n  = nt * 8 + tg * 2;
                float bn0 = sCB[n], bn1 = sCB[n + 1];
                unsigned hh, ll;
                split_fp16(fmaxf(v0 + bn0, 0.f), hh, ll); sOut[n * 148 + qA]       = hh | (ll << 16);
                split_fp16(fmaxf(v1 + bn1, 0.f), hh, ll); sOut[(n + 1) * 148 + qA] = hh | (ll << 16);
                split_fp16(fmaxf(v2 + bn0, 0.f), hh, ll); sOut[n * 148 + qB]       = hh | (ll << 16);
                split_fp16(fmaxf(v3 + bn1, 0.f), hh, ll); sOut[(n + 1) * 148 + qB] = hh | (ll << 16);
            }
        }
    }
    __syncthreads();

    // coalesced flush: each thread owns 16 consecutive u32 (one channel row
    // segment, since 144 = 9*16) -> 4 aligned uint4 loads + stores
    {
        const int i0 = tid * 16;
        const int n = i0 / 144;
        const int q0 = i0 - n * 144;
        const uint4* src = (const uint4*)(sOut + n * 148 + q0);
        uint4* dst = (uint4*)(g_h2 + (size_t)b * 9216 + i0);
        dst[0] = src[0]; dst[1] = src[1]; dst[2] = src[2]; dst[3] = src[3];
    }
}

// ---------------------------------------------------------------------------
// fc1 on tensor cores, 2-term split-fp16 (single-fp16 weights):
// BM=64, BN=64, BK=64; 128 blocks x 256 thr; warp tile m16n32.
// ---------------------------------------------------------------------------
__global__ void __launch_bounds__(256)
k_fc1(const float* __restrict__ bias) {
    __shared__ unsigned As[64][68];
    __shared__ unsigned Bs[32][72];

    const int tid = threadIdx.x;
    const int lane = tid & 31, warp = tid >> 5;
    const int g = lane >> 2, tg = lane & 3;
    const int mw = warp & 3, nw = warp >> 2;
    const int m0 = (blockIdx.x >> 1) * 64;
    const int n0 = (blockIdx.x & 1) * 64;

    const int ar = tid >> 2, ac = (tid & 3) * 16;
    const int br = tid >> 3, bc = (tid & 7) * 8;

    const unsigned* Ap = g_h2 + (size_t)(m0 + ar) * 9216 + ac;
    const unsigned* Bp = g_f1w + (size_t)br * 128 + n0 + bc;

    float C[4][4];
#pragma unroll
    for (int i = 0; i < 4; i++)
#pragma unroll
        for (int j = 0; j < 4; j++) C[i][j] = 0.f;

    uint4 avr[4], bwr[2];
#pragma unroll
    for (int j = 0; j < 4; j++) avr[j] = ((const uint4*)Ap)[j];
#pragma unroll
    for (int j = 0; j < 2; j++) bwr[j] = ((const uint4*)Bp)[j];

#pragma unroll 1
    for (int it = 0; it < 144; it++) {
        __syncthreads();
#pragma unroll
        for (int j = 0; j < 4; j++) ((uint4*)&As[ar][ac])[j] = avr[j];
#pragma unroll
        for (int j = 0; j < 2; j++) ((uint4*)&Bs[br][bc])[j] = bwr[j];
        __syncthreads();

        if (it + 1 < 144) {
            const unsigned* ap = Ap + (it + 1) * 64;
            const unsigned* bp = Bp + (size_t)(it + 1) * 32 * 128;
#pragma unroll
            for (int j = 0; j < 4; j++) avr[j] = ((const uint4*)ap)[j];
#pragma unroll
            for (int j = 0; j < 2; j++) bwr[j] = ((const uint4*)bp)[j];
        }

#pragma unroll
        for (int ks = 0; ks < 4; ks++) {
            const int kc = ks * 16 + 2 * tg;
            const int r0 = mw * 16 + g, r1 = r0 + 8;
            unsigned ah[4], al[4];
            {
                uint2 u = *(const uint2*)&As[r0][kc];
                ah[0] = __byte_perm(u.x, u.y, 0x5410);
                al[0] = __byte_perm(u.x, u.y, 0x7632);
                uint2 v = *(const uint2*)&As[r1][kc];
                ah[1] = __byte_perm(v.x, v.y, 0x5410);
                al[1] = __byte_perm(v.x, v.y, 0x7632);
                uint2 w = *(const uint2*)&As[r0][kc + 8];
                ah[2] = __byte_perm(w.x, w.y, 0x5410);
                al[2] = __byte_perm(w.x, w.y, 0x7632);
                uint2 z = *(const uint2*)&As[r1][kc + 8];
                ah[3] = __byte_perm(z.x, z.y, 0x5410);
                al[3] = __byte_perm(z.x, z.y, 0x7632);
            }
            const int kp = ks * 8 + tg;
#pragma unroll
            for (int nt = 0; nt < 4; nt++) {
                const int n = nw * 32 + nt * 8 + g;
                unsigned b0 = Bs[kp][n], b1 = Bs[kp + 4][n];
                MMAF16(C[nt], ah, b0, b1);
                MMAF16(C[nt], al, b0, b1);
            }
        }
    }

    const int m = m0 + mw * 16 + g;
#pragma unroll
    for (int nt = 0; nt < 4; nt++) {
        const int n = n0 + nw * 32 + nt * 8 + 2 * tg;
        float b0 = bias[n], b1 = bias[n + 1];
        g_h3[(size_t)m * 128 + n]           = fmaxf(C[nt][0] + b0, 0.f);
        g_h3[(size_t)m * 128 + n + 1]       = fmaxf(C[nt][1] + b1, 0.f);
        g_h3[(size_t)(m + 8) * 128 + n]     = fmaxf(C[nt][2] + b0, 0.f);
        g_h3[(size_t)(m + 8) * 128 + n + 1] = fmaxf(C[nt][3] + b1, 0.f);
    }
}

// ---------------------------------------------------------------------------
// fc2 + GMM posterior (unchanged, passing)
// ---------------------------------------------------------------------------
__global__ void k_fc2gmm(const float* __restrict__ w2,
                         const float* __restrict__ b2,
                         const float* __restrict__ cen,
                         float* __restrict__ out) {
    extern __shared__ float sm[];
    float* sH = sm;
    float* sW = sH + 128 * 129;
    float* sB = sW + 1280;
    float* sC = sB + 16;
    float* sS = sC + 112;
    float* sD = sS + 1000;

    const int tid = threadIdx.x;
    const int b0 = blockIdx.x * 128;

    for (int i = tid; i < 16384; i += 128)
        sH[(i >> 7) * 129 + (i & 127)] = g_h3[(size_t)b0 * 128 + i];
    for (int i = tid; i < 1280; i += 128) sW[i] = w2[i];
    for (int i = tid; i < 100; i += 128) sC[i] = cen[i];
    for (int i = tid; i < 1000; i += 128) sS[i] = g_sig[i];
    if (tid < 10) { sB[tid] = b2[tid]; sD[tid] = g_det[tid]; }
    __syncthreads();

    const float* h = sH + tid * 129;

    float y[10];
#pragma unroll
    for (int j = 0; j < 10; j++) {
        float s = sB[j];
        const float* wr = sW + j * 128;
#pragma unroll 8
        for (int k = 0; k < 128; k++) s = fmaf(h[k], wr[k], s);
        y[j] = s;
    }

    float expo[10];
    float mx = -3.4e38f;
#pragma unroll 1
    for (int k = 0; k < 10; k++) {
        float diff[10];
#pragma unroll
        for (int d = 0; d < 10; d++) diff[d] = y[d] - sC[k * 10 + d];
        float dist = 0.f;
#pragma unroll
        for (int i = 0; i < 10; i++) {
            float t = 0.f;
#pragma unroll
            for (int j = 0; j < 10; j++)
                t = fmaf(sS[k * 100 + i * 10 + j], diff[j], t);
            dist = fmaf(diff[i], t, dist);
        }
        float e = -0.5f * dist;
        expo[k] = e;
        mx = fmaxf(mx, e);
    }

    float num[10];
    float sum = 0.f;
#pragma unroll
    for (int k = 0; k < 10; k++) {
        float v = sD[k] * expf(expo[k] - mx);
        num[k] = v;
        sum += v;
    }
    float inv = 1.f / sum;

    float* op = out + (size_t)(b0 + tid) * 10;
#pragma unroll
    for (int k = 0; k < 10; k++) op[k] = num[k] * inv;
}

// ---------------------------------------------------------------------------
// kernel_launch
// ---------------------------------------------------------------------------
extern "C" void kernel_launch(void* const* d_in, const int* in_sizes, int n_in,
                              void* d_out, int out_size) {
    const float* x   = (const float*)d_in[0];
    const float* w1  = (const float*)d_in[1];
    const float* b1  = (const float*)d_in[2];
    const float* w2  = (const float*)d_in[3];
    const float* b2  = (const float*)d_in[4];
    const float* fw1 = (const float*)d_in[5];
    const float* fb1 = (const float*)d_in[6];
    const float* fw2 = (const float*)d_in[7];
    const float* fb2 = (const float*)d_in[8];
    const float* cen = (const float*)d_in[9];
    const float* raw = (const float*)d_in[10];
    float* out = (float*)d_out;

    const int SMEM_CONV = 171584;   // sCB now 64 floats
    const int SMEM_GMM  = (128 * 129 + 1280 + 16 + 112 + 1000 + 16) * 4;
    cudaFuncSetAttribute(k_convfused, cudaFuncAttributeMaxDynamicSharedMemorySize, SMEM_CONV);
    cudaFuncSetAttribute(k_fc2gmm,    cudaFuncAttributeMaxDynamicSharedMemorySize, SMEM_GMM);

    k_gmm_pre<<<1, 32>>>(raw);
    k_wprep<<<(9216 + 255) / 256, 256>>>(w2);
    k_f1prep<<<144, 256>>>(fw1);
    k_convfused<<<BATCH, 576, SMEM_CONV>>>(x, w1, b1, b2);
    k_fc1<<<128, 256>>>(fb1);
    k_fc2gmm<<<BATCH / 128, 128, SMEM_GMM>>>(fw2, fb2, cen, out);
}

// round 17
// speedup vs baseline: 1.0642x; 1.0642x over previous
#include <cuda_runtime.h>
#include <cuda_fp16.h>
#include <cstddef>

#define BATCH 4096

// ---------------------------------------------------------------------------
// Scratch (static __device__; no cudaMalloc allowed)
// ---------------------------------------------------------------------------
__device__ unsigned g_h2[(size_t)BATCH * 9216];   // conv2+pool out, packed (hi|lo<<16) split-fp16
__device__ float    g_h3[(size_t)BATCH * 128];    // fc1 out
__device__ float    g_sig[10 * 10 * 10];          // Sigma_inv
__device__ float    g_det[10];                    // det_scale
__device__ unsigned g_wph[9216];                  // conv2 W (single fp16), uint4 layout [ks][ntp][lane][4]
__device__ unsigned g_f1w[4608 * 128];            // fc1 W single fp16, paired fp16x2 [k/2][n]

// ---------------------------------------------------------------------------
// helpers
// ---------------------------------------------------------------------------
__device__ __forceinline__ void split_fp16(float v, unsigned& h, unsigned& l) {
    __half hb = __float2half_rn(v);
    float hf = __half2float(hb);
    __half lb = __float2half_rn(v - hf);
    h = (unsigned)__half_as_ushort(hb);
    l = (unsigned)__half_as_ushort(lb);
}

#define MMAF16(Cr, Ar, b0, b1)                                                \
    asm volatile("mma.sync.aligned.m16n8k16.row.col.f32.f16.f16.f32 "         \
                 "{%0,%1,%2,%3}, {%4,%5,%6,%7}, {%8,%9}, {%0,%1,%2,%3};"      \
                 : "+f"(Cr[0]), "+f"(Cr[1]), "+f"(Cr[2]), "+f"(Cr[3])         \
                 : "r"(Ar[0]), "r"(Ar[1]), "r"(Ar[2]), "r"(Ar[3]),            \
                   "r"(b0), "r"(b1))

// ---------------------------------------------------------------------------
// GMM precompute (unchanged)
// ---------------------------------------------------------------------------
__global__ void k_gmm_pre(const float* __restrict__ raw) {
    int k = threadIdx.x;
    if (k >= 10) return;
    const float* R = raw + k * 100;

    float D[10];
#pragma unroll
    for (int i = 0; i < 10; i++) { float r = R[i * 10 + i]; D[i] = r * r + 1e-4f; }

    float Li[10][10];
#pragma unroll
    for (int i = 0; i < 10; i++)
#pragma unroll
        for (int j = 0; j < 10; j++) Li[i][j] = (i == j) ? 1.f : 0.f;

    for (int j = 0; j < 10; j++)
        for (int i = j + 1; i < 10; i++) {
            float s = 0.f;
            for (int m = j; m < i; m++) s = fmaf(R[i * 10 + m], Li[m][j], s);
            Li[i][j] = -s;
        }

    for (int i = 0; i < 10; i++)
        for (int j = 0; j < 10; j++) {
            int a0 = (i > j) ? i : j;
            float s = 0.f;
            for (int a = a0; a < 10; a++) s += Li[a][i] * Li[a][j] / D[a];
            g_sig[k * 100 + i * 10 + j] = s;
        }

    float p = 1.f;
#pragma unroll
    for (int a = 0; a < 10; a++) p *= D[a];
    g_det[k] = rsqrtf(p);
}

// ---------------------------------------------------------------------------
// conv2 weight prep, uint4-load layout (single fp16 per weight).
// ---------------------------------------------------------------------------
__global__ void k_wprep(const float* __restrict__ w2) {
    int t = blockIdx.x * 256 + threadIdx.x;
    if (t >= 9216) return;
    int j    = t & 3;
    int lane = (t >> 2) & 31;
    int ntp  = (t >> 7) & 3;
    int ks   = t >> 9;
    int g = lane >> 2, tg = lane & 3;
    int h = j & 1, nt = 2 * ntp + (j >> 1);

    int kp = ks * 8 + h * 4 + tg;
    int n  = nt * 8 + g;
    int w  = kp >> 4;
    int ci = (kp & 15) * 2;
    int dy = w / 3, dx = w - dy * 3;

    unsigned v0 = (unsigned)__half_as_ushort(
        __float2half_rn(w2[((n * 32 + ci) * 3 + dy) * 3 + dx]));
    unsigned v1 = (unsigned)__half_as_ushort(
        __float2half_rn(w2[((n * 32 + ci + 1) * 3 + dy) * 3 + dx]));
    g_wph[t] = v0 | (v1 << 16);
}

// ---------------------------------------------------------------------------
// fc1 weight prep: single fp16 pairs [k/2][n]
// ---------------------------------------------------------------------------
__global__ void k_f1prep(const float* __restrict__ W) {
    __shared__ unsigned sh[32][132];
    const int kp0 = blockIdx.x * 32;      // 144 blocks
    const int t = threadIdx.x;            // 256
    const int n = t >> 1, half = t & 1;

    const float* src = W + (size_t)n * 9216 + kp0 * 2 + half * 32;
#pragma unroll
    for (int j = 0; j < 16; j++) {
        unsigned h0 = (unsigned)__half_as_ushort(__float2half_rn(src[2 * j]));
        unsigned h1 = (unsigned)__half_as_ushort(__float2half_rn(src[2 * j + 1]));
        sh[half * 16 + j][n] = h0 | (h1 << 16);
    }
    __syncthreads();

    const int kpl = t >> 3, c0 = (t & 7) * 16;
    unsigned* dh = &g_f1w[(size_t)(kp0 + kpl) * 128 + c0];
#pragma unroll
    for (int j = 0; j < 4; j++)
        ((uint4*)dh)[j] = ((uint4*)&sh[kpl][c0])[j];
}

// ---------------------------------------------------------------------------
// Fused conv1 + conv2 + relu + maxpool, 2-term split-fp16 HMMA.
// One block = one image, 576 threads (18 warps), 2 m16-strips x 8 n8-tiles.
// Epilogue: DIRECT scattered stores (R13 form — measured fastest; stores are
// fire-and-forget, staging cost more than it saved). conv2 bias in smem.
// ---------------------------------------------------------------------------
__global__ void __launch_bounds__(576, 1)
k_convfused(const float* __restrict__ x,
            const float* __restrict__ w1,
            const float* __restrict__ b1,
            const float* __restrict__ cb) {
    const int b   = blockIdx.x;
    const int tid = threadIdx.x;
    const int lane = tid & 31, wid = tid >> 5;
    const int g = lane >> 2, tg = lane & 3;

    extern __shared__ char smraw[];
    unsigned short* sAh = (unsigned short*)smraw;               // [676][34] u16 (fp16 hi)
    unsigned short* sAl = (unsigned short*)(smraw + 46080);     // [676][34] u16 (fp16 lo)
    unsigned* sB  = (unsigned*)(smraw + 92160);                 // [9216] u32 (fp16x2 W)
    float*    sX  = (float*)(smraw + 129024);                   // [784]
    float*    sW1 = (float*)(smraw + 132160);                   // [288]
    float*    sB1 = (float*)(smraw + 133312);                   // [32]
    float*    sCB = (float*)(smraw + 133440);                   // [64] conv2 bias
    const unsigned* sA32h = (const unsigned*)sAh;
    const unsigned* sA32l = (const unsigned*)sAl;

    for (int i = tid; i < 9216; i += 576) sB[i] = g_wph[i];
    for (int i = tid; i < 784; i += 576) sX[i] = x[(size_t)b * 784 + i];
    if (tid < 288) sW1[tid] = w1[tid];
    if (tid < 32) sB1[tid] = b1[tid];
    if (tid < 64) sCB[tid] = cb[tid];
    __syncthreads();

    // conv1 -> relu -> split-fp16, channel-interleaved
    for (int idx = tid; idx < 21632; idx += 576) {
        int c = idx / 676, p = idx - c * 676;
        int y = p / 26, xx = p - y * 26;
        float acc = sB1[c];
        const float* xp = sX + y * 28 + xx;
        const float* wp = sW1 + c * 9;
#pragma unroll
        for (int dy = 0; dy < 3; dy++)
#pragma unroll
            for (int dx = 0; dx < 3; dx++)
                acc = fmaf(xp[dy * 28 + dx], wp[dy * 3 + dx], acc);
        float v = fmaxf(acc, 0.f);
        unsigned h, l; split_fp16(v, h, l);
        sAh[p * 34 + c] = (unsigned short)h;
        sAl[p * 34 + c] = (unsigned short)l;
    }
    __syncthreads();

    // per-(strip,row-half) A row base * 17 (u32 stride of a 34-u16 row)
    int base17[2][2];
#pragma unroll
    for (int st = 0; st < 2; st++)
#pragma unroll
        for (int h = 0; h < 2; h++) {
            int m = (wid * 2 + st) * 16 + g + h * 8;
            int quad = m >> 2, e = m & 3;
            int py = quad / 12, px = quad - py * 12;
            base17[st][h] = ((py * 2 + (e >> 1)) * 26 + px * 2 + (e & 1)) * 17;
        }

    float C[2][8][4];
#pragma unroll
    for (int st = 0; st < 2; st++)
#pragma unroll
        for (int nt = 0; nt < 8; nt++)
#pragma unroll
            for (int q = 0; q < 4; q++) C[st][nt][q] = 0.f;

#pragma unroll 1
    for (int ks = 0; ks < 18; ks++) {
        const int w = ks >> 1;
        const int dy = w / 3;
        const int off17 = (dy * 26 + (w - dy * 3)) * 17;
        const int cA = (ks & 1) * 8 + tg;

        // ---- hoisted A fragments for both strips (16 regs: xh and xl) ----
        unsigned ah[2][4], al[2][4];
#pragma unroll
        for (int st = 0; st < 2; st++) {
            const int r0 = base17[st][0] + off17 + cA;
            const int r1 = base17[st][1] + off17 + cA;
            ah[st][0] = sA32h[r0];     al[st][0] = sA32l[r0];
            ah[st][1] = sA32h[r1];     al[st][1] = sA32l[r1];
            ah[st][2] = sA32h[r0 + 4]; al[st][2] = sA32l[r0 + 4];
            ah[st][3] = sA32h[r1 + 4]; al[st][3] = sA32l[r1 + 4];
        }

        // ---- n-tile pairs: one LDS.128 then 8 MMAs (same-C spacing 4) ----
        const uint4* bp = ((const uint4*)sB) + ks * 128 + lane;
#pragma unroll
        for (int ntp = 0; ntp < 4; ntp++) {
            const uint4 Bq = bp[ntp * 32];
            const int nt0 = 2 * ntp, nt1 = nt0 + 1;
            MMAF16(C[0][nt0], ah[0], Bq.x, Bq.y);
            MMAF16(C[1][nt0], ah[1], Bq.x, Bq.y);
            MMAF16(C[0][nt1], ah[0], Bq.z, Bq.w);
            MMAF16(C[1][nt1], ah[1], Bq.z, Bq.w);
            MMAF16(C[0][nt0], al[0], Bq.x, Bq.y);
            MMAF16(C[1][nt0], al[1], Bq.x, Bq.y);
            MMAF16(C[0][nt1], al[0], Bq.z, Bq.w);
            MMAF16(C[1][nt1], al[1], Bq.z, Bq.w);
        }
    }

    // maxpool via shfl + bias + relu + split-fp16 pack, direct store
#pragma unroll
    for (int st = 0; st < 2; st++) {
        const int s = wid * 2 + st;
#pragma unroll
        for (int nt = 0; nt < 8; nt++) {
            float v0 = C[st][nt][0], v1 = C[st][nt][1];
            float v2 = C[st][nt][2], v3 = C[st][nt][3];
            v0 = fmaxf(v0, __shfl_xor_sync(0xffffffffu, v0, 4));
            v0 = fmaxf(v0, __shfl_xor_sync(0xffffffffu, v0, 8));
            v1 = fmaxf(v1, __shfl_xor_sync(0xffffffffu, v1, 4));
            v1 = fmaxf(v1, __shfl_xor_sync(0xffffffffu, v1, 8));
            v2 = fmaxf(v2, __shfl_xor_sync(0xffffffffu, v2, 4));
            v2 = fmaxf(v2, __shfl_xor_sync(0xffffffffu, v2, 8));
            v3 = fmaxf(v3, __shfl_xor_sync(0xffffffffu, v3, 4));
            v3 = fmaxf(v3, __shfl_xor_sync(0xffffffffu, v3, 8));
            if ((lane & 12) == 0) {
                int a  = lane >> 4;
                int qA = s * 4 + a, qB = qA + 2;
                int n  = nt * 8 + tg * 2;
                float bn0 = sCB[n], bn1 = sCB[n + 1];
                unsigned* o = g_h2 + ((size_t)b * 64 + n) * 144;
                unsigned hh, ll;
                split_fp16(fmaxf(v0 + bn0, 0.f), hh, ll); o[qA]       = hh | (ll << 16);
                split_fp16(fmaxf(v1 + bn1, 0.f), hh, ll); o[144 + qA] = hh | (ll << 16);
                split_fp16(fmaxf(v2 + bn0, 0.f), hh, ll); o[qB]       = hh | (ll << 16);
                split_fp16(fmaxf(v3 + bn1, 0.f), hh, ll); o[144 + qB] = hh | (ll << 16);
            }
        }
    }
}

// ---------------------------------------------------------------------------
// fc1 on tensor cores, 2-term split-fp16 (single-fp16 weights):
// BM=64, BN=64, BK=64; 128 blocks x 256 thr; warp tile m16n32.
// ---------------------------------------------------------------------------
__global__ void __launch_bounds__(256)
k_fc1(const float* __restrict__ bias) {
    __shared__ unsigned As[64][68];
    __shared__ unsigned Bs[32][72];

    const int tid = threadIdx.x;
    const int lane = tid & 31, warp = tid >> 5;
    const int g = lane >> 2, tg = lane & 3;
    const int mw = warp & 3, nw = warp >> 2;
    const int m0 = (blockIdx.x >> 1) * 64;
    const int n0 = (blockIdx.x & 1) * 64;

    const int ar = tid >> 2, ac = (tid & 3) * 16;
    const int br = tid >> 3, bc = (tid & 7) * 8;

    const unsigned* Ap = g_h2 + (size_t)(m0 + ar) * 9216 + ac;
    const unsigned* Bp = g_f1w + (size_t)br * 128 + n0 + bc;

    float C[4][4];
#pragma unroll
    for (int i = 0; i < 4; i++)
#pragma unroll
        for (int j = 0; j < 4; j++) C[i][j] = 0.f;

    uint4 avr[4], bwr[2];
#pragma unroll
    for (int j = 0; j < 4; j++) avr[j] = ((const uint4*)Ap)[j];
#pragma unroll
    for (int j = 0; j < 2; j++) bwr[j] = ((const uint4*)Bp)[j];

#pragma unroll 1
    for (int it = 0; it < 144; it++) {
        __syncthreads();
#pragma unroll
        for (int j = 0; j < 4; j++) ((uint4*)&As[ar][ac])[j] = avr[j];
#pragma unroll
        for (int j = 0; j < 2; j++) ((uint4*)&Bs[br][bc])[j] = bwr[j];
        __syncthreads();

        if (it + 1 < 144) {
            const unsigned* ap = Ap + (it + 1) * 64;
            const unsigned* bp = Bp + (size_t)(it + 1) * 32 * 128;
#pragma unroll
            for (int j = 0; j < 4; j++) avr[j] = ((const uint4*)ap)[j];
#pragma unroll
            for (int j = 0; j < 2; j++) bwr[j] = ((const uint4*)bp)[j];
        }

#pragma unroll
        for (int ks = 0; ks < 4; ks++) {
            const int kc = ks * 16 + 2 * tg;
            const int r0 = mw * 16 + g, r1 = r0 + 8;
            unsigned ah[4], al[4];
            {
                uint2 u = *(const uint2*)&As[r0][kc];
                ah[0] = __byte_perm(u.x, u.y, 0x5410);
                al[0] = __byte_perm(u.x, u.y, 0x7632);
                uint2 v = *(const uint2*)&As[r1][kc];
                ah[1] = __byte_perm(v.x, v.y, 0x5410);
                al[1] = __byte_perm(v.x, v.y, 0x7632);
                uint2 w = *(const uint2*)&As[r0][kc + 8];
                ah[2] = __byte_perm(w.x, w.y, 0x5410);
                al[2] = __byte_perm(w.x, w.y, 0x7632);
                uint2 z = *(const uint2*)&As[r1][kc + 8];
                ah[3] = __byte_perm(z.x, z.y, 0x5410);
                al[3] = __byte_perm(z.x, z.y, 0x7632);
            }
            const int kp = ks * 8 + tg;
#pragma unroll
            for (int nt = 0; nt < 4; nt++) {
                const int n = nw * 32 + nt * 8 + g;
                unsigned b0 = Bs[kp][n], b1 = Bs[kp + 4][n];
                MMAF16(C[nt], ah, b0, b1);
                MMAF16(C[nt], al, b0, b1);
            }
        }
    }

    const int m = m0 + mw * 16 + g;
#pragma unroll
    for (int nt = 0; nt < 4; nt++) {
        const int n = n0 + nw * 32 + nt * 8 + 2 * tg;
        float b0 = bias[n], b1 = bias[n + 1];
        g_h3[(size_t)m * 128 + n]           = fmaxf(C[nt][0] + b0, 0.f);
        g_h3[(size_t)m * 128 + n + 1]       = fmaxf(C[nt][1] + b1, 0.f);
        g_h3[(size_t)(m + 8) * 128 + n]     = fmaxf(C[nt][2] + b0, 0.f);
        g_h3[(size_t)(m + 8) * 128 + n + 1] = fmaxf(C[nt][3] + b1, 0.f);
    }
}

// ---------------------------------------------------------------------------
// fc2 + GMM posterior (unchanged, passing)
// ---------------------------------------------------------------------------
__global__ void k_fc2gmm(const float* __restrict__ w2,
                         const float* __restrict__ b2,
                         const float* __restrict__ cen,
                         float* __restrict__ out) {
    extern __shared__ float sm[];
    float* sH = sm;
    float* sW = sH + 128 * 129;
    float* sB = sW + 1280;
    float* sC = sB + 16;
    float* sS = sC + 112;
    float* sD = sS + 1000;

    const int tid = threadIdx.x;
    const int b0 = blockIdx.x * 128;

    for (int i = tid; i < 16384; i += 128)
        sH[(i >> 7) * 129 + (i & 127)] = g_h3[(size_t)b0 * 128 + i];
    for (int i = tid; i < 1280; i += 128) sW[i] = w2[i];
    for (int i = tid; i < 100; i += 128) sC[i] = cen[i];
    for (int i = tid; i < 1000; i += 128) sS[i] = g_sig[i];
    if (tid < 10) { sB[tid] = b2[tid]; sD[tid] = g_det[tid]; }
    __syncthreads();

    const float* h = sH + tid * 129;

    float y[10];
#pragma unroll
    for (int j = 0; j < 10; j++) {
        float s = sB[j];
        const float* wr = sW + j * 128;
#pragma unroll 8
        for (int k = 0; k < 128; k++) s = fmaf(h[k], wr[k], s);
        y[j] = s;
    }

    float expo[10];
    float mx = -3.4e38f;
#pragma unroll 1
    for (int k = 0; k < 10; k++) {
        float diff[10];
#pragma unroll
        for (int d = 0; d < 10; d++) diff[d] = y[d] - sC[k * 10 + d];
        float dist = 0.f;
#pragma unroll
        for (int i = 0; i < 10; i++) {
            float t = 0.f;
#pragma unroll
            for (int j = 0; j < 10; j++)
                t = fmaf(sS[k * 100 + i * 10 + j], diff[j], t);
            dist = fmaf(diff[i], t, dist);
        }
        float e = -0.5f * dist;
        expo[k] = e;
        mx = fmaxf(mx, e);
    }

    float num[10];
    float sum = 0.f;
#pragma unroll
    for (int k = 0; k < 10; k++) {
        float v = sD[k] * expf(expo[k] - mx);
        num[k] = v;
        sum += v;
    }
    float inv = 1.f / sum;

    float* op = out + (size_t)(b0 + tid) * 10;
#pragma unroll
    for (int k = 0; k < 10; k++) op[k] = num[k] * inv;
}

// ---------------------------------------------------------------------------
// kernel_launch
// ---------------------------------------------------------------------------
extern "C" void kernel_launch(void* const* d_in, const int* in_sizes, int n_in,
                              void* d_out, int out_size) {
    const float* x   = (const float*)d_in[0];
    const float* w1  = (const float*)d_in[1];
    const float* b1  = (const float*)d_in[2];
    const float* w2  = (const float*)d_in[3];
    const float* b2  = (const float*)d_in[4];
    const float* fw1 = (const float*)d_in[5];
    const float* fb1 = (const float*)d_in[6];
    const float* fw2 = (const float*)d_in[7];
    const float* fb2 = (const float*)d_in[8];
    const float* cen = (const float*)d_in[9];
    const float* raw = (const float*)d_in[10];
    float* out = (float*)d_out;

    const int SMEM_CONV = 133696;
    const int SMEM_GMM  = (128 * 129 + 1280 + 16 + 112 + 1000 + 16) * 4;
    cudaFuncSetAttribute(k_convfused, cudaFuncAttributeMaxDynamicSharedMemorySize, SMEM_CONV);
    cudaFuncSetAttribute(k_fc2gmm,    cudaFuncAttributeMaxDynamicSharedMemorySize, SMEM_GMM);

    k_gmm_pre<<<1, 32>>>(raw);
    k_wprep<<<(9216 + 255) / 256, 256>>>(w2);
    k_f1prep<<<144, 256>>>(fw1);
    k_convfused<<<BATCH, 576, SMEM_CONV>>>(x, w1, b1, b2);
    k_fc1<<<128, 256>>>(fb1);
    k_fc2gmm<<<BATCH / 128, 128, SMEM_GMM>>>(fw2, fb2, cen, out);
}